// round 11
// baseline (speedup 1.0000x reference)
#include <cuda_runtime.h>
#include <cuda_bf16.h>
#include <cstdint>

#define N_NODES 50000
#define N_EDGES 600000
#define DIM 128
#define CAP 64
#define OVMAX 8192

// Device scratch (zero-init at load; invariants restored each call)
__device__ float g_deg[N_NODES];                    // reset in k_dinv
__device__ float g_dinv[N_NODES];
__device__ float g_y[(size_t)N_NODES * DIM];        // y = x @ W^T
__device__ int   g_cnt[N_NODES];                    // reset in k_aggregate
__device__ int2  g_ebuck[(size_t)N_NODES * CAP];
__device__ int   g_ovcnt;
__device__ int   g_ovuse;
__device__ int   g_ovt[OVMAX];
__device__ int2  g_ovsw[OVMAX];

__device__ __forceinline__ void mma16816bf(float& c0, float& c1, float& c2, float& c3,
                                           uint32_t a0, uint32_t a1, uint32_t a2, uint32_t a3,
                                           uint32_t b0, uint32_t b1) {
    asm volatile("mma.sync.aligned.m16n8k16.row.col.f32.bf16.bf16.f32 "
                 "{%0,%1,%2,%3}, {%4,%5,%6,%7}, {%8,%9}, {%0,%1,%2,%3};"
                 : "+f"(c0), "+f"(c1), "+f"(c2), "+f"(c3)
                 : "r"(a0), "r"(a1), "r"(a2), "r"(a3), "r"(b0), "r"(b1));
}

__device__ __forceinline__ uint32_t pkh(float a, float b, float& ra, float& rb) {
    __nv_bfloat16 ha = __float2bfloat16(a);
    __nv_bfloat16 hb = __float2bfloat16(b);
    ra = a - __bfloat162float(ha);
    rb = b - __bfloat162float(hb);
    __nv_bfloat162 h2(ha, hb);
    return *(uint32_t*)&h2;
}
__device__ __forceinline__ uint32_t pk0(float a, float b) {
    __nv_bfloat162 h2(__float2bfloat16(a), __float2bfloat16(b));
    return *(uint32_t*)&h2;
}

// =====================================================================
// Fused kernel with INTERLEAVED roles:
//   odd bid < 2*EB           -> edge block (eb = bid>>1)
//   even bid < 2*EB          -> GEMM tile  (gb = bid>>1)
//   bid >= 2*EB              -> GEMM tile  (gb = bid - EB)
// Every scheduling wave mixes edge (L2/atomic) and GEMM (tensor/smem)
// blocks so the two phases overlap instead of running in separate waves.
// GEMM: 256 thr = 8 warps 4x2, 32x64 warp tiles, K chunk 16, m16n8k16
// bf16 3-term split (xh*Wh + xl*Wh + xh*Wl), pitch-12 fragment smem.
// =====================================================================
#define SP 12
__global__ __launch_bounds__(256, 2) void k_fused(const float* __restrict__ x,
                                                  const float* __restrict__ W,
                                                  const void* __restrict__ ei,
                                                  const float* __restrict__ ew,
                                                  int M, int E, int GB, int EB) {
    int bid = blockIdx.x;
    bool is_edge = (bid & 1) && ((bid >> 1) < EB);

    if (!is_edge) {
        // ---------------- GEMM tile ----------------
        int gb = (bid < 2 * EB) ? (bid >> 1) : (bid - EB);
        __shared__ uint32_t Ah[128 * SP], Al[128 * SP];
        __shared__ uint32_t Bh[128 * SP], Bl[128 * SP];

        int tid = threadIdx.x;
        int lane = tid & 31;
        int wrp = tid >> 5;
        int wm = wrp & 3;
        int wn = wrp >> 2;
        int rowBase = gb * 128;

        int g  = lane >> 2;
        int tg = lane & 3;

        float acc[2][8][4];
        #pragma unroll
        for (int mt = 0; mt < 2; mt++)
            #pragma unroll
            for (int nt = 0; nt < 8; nt++)
                #pragma unroll
                for (int c = 0; c < 4; c++) acc[mt][nt][c] = 0.0f;

        int srow = tid >> 1;
        int shalf = tid & 1;
        int sbase = shalf * 4;

        float4 pa0, pa1, pb0, pb1;
        {
            int gm = rowBase + srow;
            const float* xr = x + (size_t)gm * DIM + shalf * 8;
            const float* wr = W + (size_t)srow * DIM + shalf * 8;
            if (gm < M) { pa0 = *(const float4*)xr; pa1 = *(const float4*)(xr + 4); }
            else { pa0 = make_float4(0,0,0,0); pa1 = make_float4(0,0,0,0); }
            pb0 = *(const float4*)wr; pb1 = *(const float4*)(wr + 4);
        }

        #pragma unroll
        for (int kt = 0; kt < DIM; kt += 16) {
            {
                float a[8] = {pa0.x, pa0.y, pa0.z, pa0.w, pa1.x, pa1.y, pa1.z, pa1.w};
                float b[8] = {pb0.x, pb0.y, pb0.z, pb0.w, pb1.x, pb1.y, pb1.z, pb1.w};
                int rw = srow * SP + sbase;
                #pragma unroll
                for (int i = 0; i < 4; i++) {
                    float r0, r1, s0, s1;
                    Ah[rw + i] = pkh(a[2 * i], a[2 * i + 1], r0, r1);
                    Al[rw + i] = pk0(r0, r1);
                    Bh[rw + i] = pkh(b[2 * i], b[2 * i + 1], s0, s1);
                    Bl[rw + i] = pk0(s0, s1);
                }
            }
            __syncthreads();

            if (kt + 16 < DIM) {
                int gm = rowBase + srow;
                const float* xr = x + (size_t)gm * DIM + kt + 16 + shalf * 8;
                const float* wr = W + (size_t)srow * DIM + kt + 16 + shalf * 8;
                if (gm < M) { pa0 = *(const float4*)xr; pa1 = *(const float4*)(xr + 4); }
                else { pa0 = make_float4(0,0,0,0); pa1 = make_float4(0,0,0,0); }
                pb0 = *(const float4*)wr; pb1 = *(const float4*)(wr + 4);
            }

            uint32_t ah[2][4], al[2][4];
            #pragma unroll
            for (int mt = 0; mt < 2; mt++) {
                int r0 = (wm * 32 + mt * 16 + g) * SP;
                int r1 = r0 + 8 * SP;
                ah[mt][0] = Ah[r0 + tg];     ah[mt][1] = Ah[r1 + tg];
                ah[mt][2] = Ah[r0 + tg + 4]; ah[mt][3] = Ah[r1 + tg + 4];
                al[mt][0] = Al[r0 + tg];     al[mt][1] = Al[r1 + tg];
                al[mt][2] = Al[r0 + tg + 4]; al[mt][3] = Al[r1 + tg + 4];
            }
            #pragma unroll
            for (int nt = 0; nt < 8; nt++) {
                int nb = (wn * 64 + nt * 8 + g) * SP;
                uint32_t bh0 = Bh[nb + tg], bh1 = Bh[nb + tg + 4];
                uint32_t bl0 = Bl[nb + tg], bl1 = Bl[nb + tg + 4];
                #pragma unroll
                for (int mt = 0; mt < 2; mt++) {
                    float* c = acc[mt][nt];
                    mma16816bf(c[0], c[1], c[2], c[3],
                               ah[mt][0], ah[mt][1], ah[mt][2], ah[mt][3], bh0, bh1);
                    mma16816bf(c[0], c[1], c[2], c[3],
                               ah[mt][0], ah[mt][1], ah[mt][2], ah[mt][3], bl0, bl1);
                    mma16816bf(c[0], c[1], c[2], c[3],
                               al[mt][0], al[mt][1], al[mt][2], al[mt][3], bh0, bh1);
                }
            }
            __syncthreads();
        }

        #pragma unroll
        for (int mt = 0; mt < 2; mt++) {
            int row0 = rowBase + wm * 32 + mt * 16 + g;
            #pragma unroll
            for (int nt = 0; nt < 8; nt++) {
                int col = wn * 64 + nt * 8 + 2 * tg;
                float* c = acc[mt][nt];
                if (row0 < M)
                    *(float2*)(g_y + (size_t)row0 * DIM + col) = make_float2(c[0], c[1]);
                if (row0 + 8 < M)
                    *(float2*)(g_y + (size_t)(row0 + 8) * DIM + col) = make_float2(c[2], c[3]);
            }
        }
    } else {
        // ---------------- edge block ----------------
        int b = bid >> 1;
        int chunk = (E + EB - 1) / EB;
        int beg = b * chunk;
        int end = beg + chunk; if (end > E) end = E;
        if (beg >= end) return;

        __shared__ int s_is64;
        if (threadIdx.x == 0) s_is64 = 1;
        __syncthreads();
        const long long* p64 = (const long long*)ei;
        const int*       p32 = (const int*)ei;
        int samp = end - beg; if (samp > 256) samp = 256;
        if ((int)threadIdx.x < samp) {
            long long v = p64[beg + threadIdx.x];
            if (v < 0 || v >= (long long)N_NODES) s_is64 = 0;
        }
        __syncthreads();
        int is64 = s_is64;

        for (int i = beg + threadIdx.x; i < end; i += 256) {
            int s, t;
            float w = ew[i];
            if (is64) { s = (int)p64[i]; t = (int)p64[(size_t)E + i]; }
            else      { s = p32[i];      t = p32[(size_t)E + i]; }
            atomicAdd(&g_deg[s], w);
            int pos = atomicAdd(&g_cnt[t], 1);
            if (pos < CAP) {
                g_ebuck[(size_t)t * CAP + pos] = make_int2(s, __float_as_int(w));
            } else {
                int o = atomicAdd(&g_ovcnt, 1);
                if (o < OVMAX) { g_ovt[o] = t; g_ovsw[o] = make_int2(s, __float_as_int(w)); }
            }
        }
    }
}

// ---------------- dinv = rsqrt(deg + 1); reset deg; latch overflow --------
__global__ void k_dinv(int n) {
    int i = blockIdx.x * blockDim.x + threadIdx.x;
    if (i < n) {
        g_dinv[i] = rsqrtf(g_deg[i] + 1.0f);
        g_deg[i] = 0.0f;
    }
    if (i == 0) {
        int c = g_ovcnt;
        g_ovuse = (c < OVMAX) ? c : OVMAX;
        g_ovcnt = 0;
    }
}

// ---------------- pull-aggregation: warp per node -------------------------
__global__ void k_aggregate(const float* __restrict__ bias,
                            float* __restrict__ out, int n) {
    int warp = (blockIdx.x * blockDim.x + threadIdx.x) >> 5;
    int lane = threadIdx.x & 31;
    if (warp >= n) return;
    int t = warp;

    int cnt = g_cnt[t];
    if (cnt > CAP) cnt = CAP;
    const float4* y4 = (const float4*)g_y;
    const int2* buck = g_ebuck + (size_t)t * CAP;

    float di = g_dinv[t];
    float sc = di * di;
    float4 self = y4[(size_t)t * 32 + lane];
    float4 bi = ((const float4*)bias)[lane];
    float4 acc;
    acc.x = self.x * sc + bi.x;
    acc.y = self.y * sc + bi.y;
    acc.z = self.z * sc + bi.z;
    acc.w = self.w * sc + bi.w;

    int2 e_nxt = make_int2(0, 0);
    if (cnt > 0) e_nxt = buck[0];
    for (int j = 0; j < cnt; j++) {
        int2 e = e_nxt;
        if (j + 1 < cnt) e_nxt = buck[j + 1];
        float wn = __int_as_float(e.y) * g_dinv[e.x] * di;
        float4 v = y4[(size_t)e.x * 32 + lane];
        acc.x += v.x * wn;
        acc.y += v.y * wn;
        acc.z += v.z * wn;
        acc.w += v.w * wn;
    }

    int ov = g_ovuse;
    for (int i = 0; i < ov; i++) {
        if (g_ovt[i] == t) {
            int2 e = g_ovsw[i];
            float wn = __int_as_float(e.y) * g_dinv[e.x] * di;
            float4 v = y4[(size_t)e.x * 32 + lane];
            acc.x += v.x * wn;
            acc.y += v.y * wn;
            acc.z += v.z * wn;
            acc.w += v.w * wn;
        }
    }

    ((float4*)out)[(size_t)t * 32 + lane] = acc;
    if (lane == 0) g_cnt[t] = 0;
}

extern "C" void kernel_launch(void* const* d_in, const int* in_sizes, int n_in,
                              void* d_out, int out_size) {
    const float* x  = (const float*)d_in[0];
    const void*  ei = d_in[1];
    const float* ew = (const float*)d_in[2];
    const float* W  = (const float*)d_in[3];
    const float* b  = (const float*)d_in[4];
    float* out = (float*)d_out;

    int N = in_sizes[0] / DIM;
    int E = in_sizes[1] / 2;

    int GB = (N + 127) / 128;
    int EB = 296;

    k_fused<<<GB + EB, 256>>>(x, W, ei, ew, N, E, GB, EB);
    k_dinv<<<(N + 255) / 256, 256>>>(N);
    k_aggregate<<<(N * 32 + 255) / 256, 256>>>(b, out, N);
}

// round 12
// speedup vs baseline: 1.0446x; 1.0446x over previous
#include <cuda_runtime.h>
#include <cuda_bf16.h>
#include <cstdint>

#define N_NODES 50000
#define N_EDGES 600000
#define DIM 128
#define CAP 64
#define OVMAX 8192

// Device scratch (zero-init at load; invariants restored each call)
__device__ float g_deg[N_NODES];                    // reset in k_dinv
__device__ float g_dinv[N_NODES];
__device__ float g_y[(size_t)N_NODES * DIM];        // y = x @ W^T
__device__ int   g_cnt[N_NODES];                    // reset in k_aggregate
__device__ int2  g_ebuck[(size_t)N_NODES * CAP];
__device__ int   g_ovcnt;
__device__ int   g_ovuse;
__device__ int   g_ovt[OVMAX];
__device__ int2  g_ovsw[OVMAX];
// W pre-packed in m16n8k16 b-fragment order: [chunk 8][ntile 16][lane 32]
__device__ uint2 g_WfH[8 * 16 * 32];
__device__ uint2 g_WfL[8 * 16 * 32];

__device__ __forceinline__ void mma16816bf(float& c0, float& c1, float& c2, float& c3,
                                           uint32_t a0, uint32_t a1, uint32_t a2, uint32_t a3,
                                           uint32_t b0, uint32_t b1) {
    asm volatile("mma.sync.aligned.m16n8k16.row.col.f32.bf16.bf16.f32 "
                 "{%0,%1,%2,%3}, {%4,%5,%6,%7}, {%8,%9}, {%0,%1,%2,%3};"
                 : "+f"(c0), "+f"(c1), "+f"(c2), "+f"(c3)
                 : "r"(a0), "r"(a1), "r"(a2), "r"(a3), "r"(b0), "r"(b1));
}

__device__ __forceinline__ uint32_t pkh(float a, float b, float& ra, float& rb) {
    __nv_bfloat16 ha = __float2bfloat16(a);
    __nv_bfloat16 hb = __float2bfloat16(b);
    ra = a - __bfloat162float(ha);
    rb = b - __bfloat162float(hb);
    __nv_bfloat162 h2(ha, hb);
    return *(uint32_t*)&h2;
}
__device__ __forceinline__ uint32_t pk0(float a, float b) {
    __nv_bfloat162 h2(__float2bfloat16(a), __float2bfloat16(b));
    return *(uint32_t*)&h2;
}

// ---------------- prep: pack W into b-fragment order ----------------------
// For chunk c, n-tile nt (n0 = nt*8), lane l:
//   b0 = bf16x2{ W[n0+l/4][k0], W[n0+l/4][k0+1] },  k0 = c*16 + (l%4)*2
//   b1 = same with k0+8.  Hi = bf16(w), Lo = bf16(w - hi).
__global__ void k_prepW(const float* __restrict__ W) {
    int i = blockIdx.x * blockDim.x + threadIdx.x;   // 0..4095
    if (i >= 8 * 16 * 32) return;
    int l  = i & 31;
    int nt = (i >> 5) & 15;
    int c  = i >> 9;
    int n  = nt * 8 + (l >> 2);
    int k0 = c * 16 + (l & 3) * 2;
    const float* wr = W + (size_t)n * DIM;
    float r0, r1, r2, r3;
    uint32_t h0 = pkh(wr[k0], wr[k0 + 1], r0, r1);
    uint32_t h1 = pkh(wr[k0 + 8], wr[k0 + 9], r2, r3);
    g_WfH[i] = make_uint2(h0, h1);
    g_WfL[i] = make_uint2(pk0(r0, r1), pk0(r2, r3));
}

// =====================================================================
// Fused kernel: blocks [0,EB) = edge pass; blocks [EB,EB+GB) = GEMM tile.
// GEMM is SMEM-FREE: A loaded straight from x in fragment layout and
// converted in registers; B fragments LDG'd from pre-packed g_WfH/g_WfL
// (L1-resident). No STS/LDS/syncthreads; latency hidden by LDG MLP.
// 8 warps = 4(M) x 2(N) grid of 32x64 warp tiles; K chunked by 16;
// 3-term split: xh*Wh + xl*Wh + xh*Wl.
// =====================================================================
__global__ __launch_bounds__(256, 2) void k_fused(const float* __restrict__ x,
                                                  const void* __restrict__ ei,
                                                  const float* __restrict__ ew,
                                                  int M, int E, int GB, int EB) {
    int bid = blockIdx.x;
    if (bid >= EB) {
        // ---------------- GEMM tile ----------------
        int tid = threadIdx.x;
        int lane = tid & 31;
        int wrp = tid >> 5;
        int wm = wrp & 3;               // M warp tile (32 rows)
        int wn = wrp >> 2;              // N warp tile (64 cols)
        int rowBase = (bid - EB) * 128;

        int g  = lane >> 2;             // 0..7  (row within 8)
        int tg = lane & 3;              // 0..3  (k-pair)

        float acc[2][8][4];
        #pragma unroll
        for (int mt = 0; mt < 2; mt++)
            #pragma unroll
            for (int nt = 0; nt < 8; nt++)
                #pragma unroll
                for (int c = 0; c < 4; c++) acc[mt][nt][c] = 0.0f;

        int m1g[2], m2g[2];
        bool v1[2], v2[2];
        #pragma unroll
        for (int mt = 0; mt < 2; mt++) {
            int m1 = rowBase + wm * 32 + mt * 16 + g;
            m1g[mt] = m1; m2g[mt] = m1 + 8;
            v1[mt] = (m1 < M); v2[mt] = (m1 + 8 < M);
        }

        #pragma unroll
        for (int c = 0; c < 8; c++) {
            int k0 = c * 16 + tg * 2;
            // B fragments (coalesced 8B LDGs, L1-hot after wave 1)
            uint2 bh[8], bl[8];
            #pragma unroll
            for (int nt = 0; nt < 8; nt++) {
                int idx = ((c * 16 + wn * 8 + nt) << 5) + lane;
                bh[nt] = g_WfH[idx];
                bl[nt] = g_WfL[idx];
            }
            // A fragments: direct gather from x + register conversion
            uint32_t ah[2][4], al[2][4];
            #pragma unroll
            for (int mt = 0; mt < 2; mt++) {
                float2 x00 = v1[mt] ? *(const float2*)(x + (size_t)m1g[mt] * DIM + k0)     : make_float2(0.f, 0.f);
                float2 x10 = v2[mt] ? *(const float2*)(x + (size_t)m2g[mt] * DIM + k0)     : make_float2(0.f, 0.f);
                float2 x01 = v1[mt] ? *(const float2*)(x + (size_t)m1g[mt] * DIM + k0 + 8) : make_float2(0.f, 0.f);
                float2 x11 = v2[mt] ? *(const float2*)(x + (size_t)m2g[mt] * DIM + k0 + 8) : make_float2(0.f, 0.f);
                float r0, r1;
                ah[mt][0] = pkh(x00.x, x00.y, r0, r1); al[mt][0] = pk0(r0, r1);
                ah[mt][1] = pkh(x10.x, x10.y, r0, r1); al[mt][1] = pk0(r0, r1);
                ah[mt][2] = pkh(x01.x, x01.y, r0, r1); al[mt][2] = pk0(r0, r1);
                ah[mt][3] = pkh(x11.x, x11.y, r0, r1); al[mt][3] = pk0(r0, r1);
            }
            // MMAs: 3-term split
            #pragma unroll
            for (int nt = 0; nt < 8; nt++) {
                #pragma unroll
                for (int mt = 0; mt < 2; mt++) {
                    float* cc = acc[mt][nt];
                    mma16816bf(cc[0], cc[1], cc[2], cc[3],
                               ah[mt][0], ah[mt][1], ah[mt][2], ah[mt][3],
                               bh[nt].x, bh[nt].y);
                    mma16816bf(cc[0], cc[1], cc[2], cc[3],
                               ah[mt][0], ah[mt][1], ah[mt][2], ah[mt][3],
                               bl[nt].x, bl[nt].y);
                    mma16816bf(cc[0], cc[1], cc[2], cc[3],
                               al[mt][0], al[mt][1], al[mt][2], al[mt][3],
                               bh[nt].x, bh[nt].y);
                }
            }
        }

        // epilogue: write y
        #pragma unroll
        for (int mt = 0; mt < 2; mt++) {
            #pragma unroll
            for (int nt = 0; nt < 8; nt++) {
                int col = wn * 64 + nt * 8 + 2 * tg;
                float* cc = acc[mt][nt];
                if (v1[mt])
                    *(float2*)(g_y + (size_t)m1g[mt] * DIM + col) = make_float2(cc[0], cc[1]);
                if (v2[mt])
                    *(float2*)(g_y + (size_t)m2g[mt] * DIM + col) = make_float2(cc[2], cc[3]);
            }
        }
    } else {
        // ---------------- edge block ----------------
        int b = bid;
        int chunk = (E + EB - 1) / EB;
        int beg = b * chunk;
        int end = beg + chunk; if (end > E) end = E;
        if (beg >= end) return;

        __shared__ int s_is64;
        if (threadIdx.x == 0) s_is64 = 1;
        __syncthreads();
        const long long* p64 = (const long long*)ei;
        const int*       p32 = (const int*)ei;
        int samp = end - beg; if (samp > 256) samp = 256;
        if ((int)threadIdx.x < samp) {
            long long v = p64[beg + threadIdx.x];
            if (v < 0 || v >= (long long)N_NODES) s_is64 = 0;
        }
        __syncthreads();
        int is64 = s_is64;

        for (int i = beg + threadIdx.x; i < end; i += 256) {
            int s, t;
            float w = ew[i];
            if (is64) { s = (int)p64[i]; t = (int)p64[(size_t)E + i]; }
            else      { s = p32[i];      t = p32[(size_t)E + i]; }
            atomicAdd(&g_deg[s], w);
            int pos = atomicAdd(&g_cnt[t], 1);
            if (pos < CAP) {
                g_ebuck[(size_t)t * CAP + pos] = make_int2(s, __float_as_int(w));
            } else {
                int o = atomicAdd(&g_ovcnt, 1);
                if (o < OVMAX) { g_ovt[o] = t; g_ovsw[o] = make_int2(s, __float_as_int(w)); }
            }
        }
    }
}

// ---------------- dinv = rsqrt(deg + 1); reset deg; latch overflow --------
__global__ void k_dinv(int n) {
    int i = blockIdx.x * blockDim.x + threadIdx.x;
    if (i < n) {
        g_dinv[i] = rsqrtf(g_deg[i] + 1.0f);
        g_deg[i] = 0.0f;
    }
    if (i == 0) {
        int c = g_ovcnt;
        g_ovuse = (c < OVMAX) ? c : OVMAX;
        g_ovcnt = 0;
    }
}

// ---------------- pull-aggregation: warp per node -------------------------
__global__ void k_aggregate(const float* __restrict__ bias,
                            float* __restrict__ out, int n) {
    int warp = (blockIdx.x * blockDim.x + threadIdx.x) >> 5;
    int lane = threadIdx.x & 31;
    if (warp >= n) return;
    int t = warp;

    int cnt = g_cnt[t];
    if (cnt > CAP) cnt = CAP;
    const float4* y4 = (const float4*)g_y;
    const int2* buck = g_ebuck + (size_t)t * CAP;

    float di = g_dinv[t];
    float sc = di * di;
    float4 self = y4[(size_t)t * 32 + lane];
    float4 bi = ((const float4*)bias)[lane];
    float4 acc;
    acc.x = self.x * sc + bi.x;
    acc.y = self.y * sc + bi.y;
    acc.z = self.z * sc + bi.z;
    acc.w = self.w * sc + bi.w;

    int2 e_nxt = make_int2(0, 0);
    if (cnt > 0) e_nxt = buck[0];
    for (int j = 0; j < cnt; j++) {
        int2 e = e_nxt;
        if (j + 1 < cnt) e_nxt = buck[j + 1];
        float wn = __int_as_float(e.y) * g_dinv[e.x] * di;
        float4 v = y4[(size_t)e.x * 32 + lane];
        acc.x += v.x * wn;
        acc.y += v.y * wn;
        acc.z += v.z * wn;
        acc.w += v.w * wn;
    }

    int ov = g_ovuse;
    for (int i = 0; i < ov; i++) {
        if (g_ovt[i] == t) {
            int2 e = g_ovsw[i];
            float wn = __int_as_float(e.y) * g_dinv[e.x] * di;
            float4 v = y4[(size_t)e.x * 32 + lane];
            acc.x += v.x * wn;
            acc.y += v.y * wn;
            acc.z += v.z * wn;
            acc.w += v.w * wn;
        }
    }

    ((float4*)out)[(size_t)t * 32 + lane] = acc;
    if (lane == 0) g_cnt[t] = 0;
}

extern "C" void kernel_launch(void* const* d_in, const int* in_sizes, int n_in,
                              void* d_out, int out_size) {
    const float* x  = (const float*)d_in[0];
    const void*  ei = d_in[1];
    const float* ew = (const float*)d_in[2];
    const float* W  = (const float*)d_in[3];
    const float* b  = (const float*)d_in[4];
    float* out = (float*)d_out;

    int N = in_sizes[0] / DIM;
    int E = in_sizes[1] / 2;

    int GB = (N + 127) / 128;
    int EB = 296;

    k_prepW<<<16, 256>>>(W);
    k_fused<<<GB + EB, 256>>>(x, ei, ew, N, E, GB, EB);
    k_dinv<<<(N + 255) / 256, 256>>>(N);
    k_aggregate<<<(N * 32 + 255) / 256, 256>>>(b, out, N);
}